// round 4
// baseline (speedup 1.0000x reference)
#include <cuda_runtime.h>
#include <cuda_pipeline.h>

// FilterLayer: y[b,c,h,w] = sum_{i,j in 5x5} xpad[b,c,h+i,w+j] * f[b,i*5+j,h,w]
// x: [4,3,512,512] f32, f: [4,25,512,512] f32, out: [4,3,512,512] f32, pad=2.
//
// R3: bytes-in-flight fix. f staged via cp.async (register-free MLP) into a
// 4-stage smem ring, one stage = one tap-row (5 taps x 8 rows x 128 px = 20KB).
// Chunk map (tap=j, hr=ty, wc=tx) means every thread reads back exactly the
// smem it wrote -> no __syncthreads in the pipeline, only per-thread
// __pipeline_wait_prior. x tile staged once in smem (19KB). 98.6KB smem ->
// 2 blocks/SM; in-flight f bytes ~100KB/SM >> 31KB latency-BW product.

#define Hc 512
#define Wc 512
#define Bc 4
#define WIN 5
#define PAD 2

#define TILE_W 128   // 32 threads x 4 px
#define TILE_H 8
#define SW (TILE_W + 2*PAD)   // 132
#define SH (TILE_H + 2*PAD)   // 12

#define X_FLOATS (3 * SH * SW)          // 4752
#define STAGE_FLOATS (WIN * TILE_H * TILE_W)  // 5120 (20KB)
#define NSTAGE 4
#define SMEM_BYTES ((X_FLOATS + NSTAGE * STAGE_FLOATS) * 4)  // 100928

__global__ __launch_bounds__(256)
void filter_kernel(const float* __restrict__ x,
                   const float* __restrict__ f,
                   float* __restrict__ out)
{
    extern __shared__ float smem[];
    float* sx = smem;                    // [3][SH][SW]
    float* sf = smem + X_FLOATS;         // [NSTAGE][WIN][TILE_H][TILE_W]

    const int tx = threadIdx.x;          // 0..31
    const int ty = threadIdx.y;          // 0..7
    const int tid = ty * 32 + tx;
    const int b  = blockIdx.z;
    const int h0 = blockIdx.y * TILE_H;
    const int w0 = blockIdx.x * TILE_W;

    // ---- f prefetch helper: one tap-row into stage st ----
    // Thread (tx,ty) copies f[b, i*5+j, h0+ty, w0+tx*4 .. +3] for j=0..4.
    // It later reads back exactly these slots -> no barrier needed.
    auto prefetch_row = [&](int st, int i) {
        #pragma unroll
        for (int j = 0; j < WIN; j++) {
            const float* src = f + (((long)(b * (WIN*WIN) + i * WIN + j)) * Hc + (h0 + ty)) * Wc
                                 + w0 + tx * 4;
            float* dst = sf + st * STAGE_FLOATS + (j * TILE_H + ty) * TILE_W + tx * 4;
            __pipeline_memcpy_async(dst, src, 16);
        }
        __pipeline_commit();
    };

    // Kick off f loads for tap-rows 0..2 first (DRAM busy ASAP)
    prefetch_row(0, 0);
    prefetch_row(1, 1);
    prefetch_row(2, 2);

    // ---- Stage x tile (with zero halo) into shared ----
    #pragma unroll 4
    for (int idx = tid; idx < X_FLOATS; idx += 256) {
        int c   = idx / (SH * SW);
        int rem = idx - c * (SH * SW);
        int r   = rem / SW;
        int col = rem - r * SW;
        int gh = h0 + r - PAD;
        int gw = w0 + col - PAD;
        float v = 0.0f;
        if ((unsigned)gh < Hc && (unsigned)gw < Wc)
            v = x[((b * 3 + c) * Hc + gh) * Wc + gw];
        sx[(c * SH + r) * SW + col] = v;
    }
    __syncthreads();   // x tile visible to all (only barrier in the kernel)

    float acc[3][4];
    #pragma unroll
    for (int c = 0; c < 3; c++)
        #pragma unroll
        for (int p = 0; p < 4; p++)
            acc[c][p] = 0.0f;

    #pragma unroll
    for (int i = 0; i < WIN; i++) {
        // Wait until tap-row i's cp.async group has landed (per-thread).
        __pipeline_wait_prior(i < 2 ? 2 : (WIN - 1 - i));

        // Prefetch tap-row i+3 into ring slot (i+3)&3 (distinct from slot i&3;
        // its previous contents (row i-1) were fully consumed last iteration).
        if (i + 3 < WIN) prefetch_row((i + 3) & (NSTAGE - 1), i + 3);

        const int st = i & (NSTAGE - 1);
        float4 fv[WIN];
        #pragma unroll
        for (int j = 0; j < WIN; j++)
            fv[j] = *reinterpret_cast<const float4*>(
                sf + st * STAGE_FLOATS + (j * TILE_H + ty) * TILE_W + tx * 4);

        #pragma unroll
        for (int c = 0; c < 3; c++) {
            const float* row = sx + ((c * SH) + ty + i) * SW + tx * 4;
            const float4 a  = *reinterpret_cast<const float4*>(row);
            const float4 bb = *reinterpret_cast<const float4*>(row + 4);
            float xr[8];
            xr[0] = a.x;  xr[1] = a.y;  xr[2] = a.z;  xr[3] = a.w;
            xr[4] = bb.x; xr[5] = bb.y; xr[6] = bb.z; xr[7] = bb.w;

            #pragma unroll
            for (int j = 0; j < WIN; j++) {
                acc[c][0] = fmaf(xr[0 + j], fv[j].x, acc[c][0]);
                acc[c][1] = fmaf(xr[1 + j], fv[j].y, acc[c][1]);
                acc[c][2] = fmaf(xr[2 + j], fv[j].z, acc[c][2]);
                acc[c][3] = fmaf(xr[3 + j], fv[j].w, acc[c][3]);
            }
        }
    }

    const int h = h0 + ty;
    const int w = w0 + tx * 4;
    #pragma unroll
    for (int c = 0; c < 3; c++) {
        float4 o;
        o.x = acc[c][0]; o.y = acc[c][1]; o.z = acc[c][2]; o.w = acc[c][3];
        __stcs(reinterpret_cast<float4*>(out + ((long)(b * 3 + c) * Hc + h) * Wc + w), o);
    }
}

extern "C" void kernel_launch(void* const* d_in, const int* in_sizes, int n_in,
                              void* d_out, int out_size)
{
    const float* x = (const float*)d_in[0];
    const float* f = (const float*)d_in[1];
    float* out = (float*)d_out;

    cudaFuncSetAttribute(filter_kernel,
                         cudaFuncAttributeMaxDynamicSharedMemorySize, SMEM_BYTES);

    dim3 block(32, 8, 1);
    dim3 grid(Wc / TILE_W, Hc / TILE_H, Bc);
    filter_kernel<<<grid, block, SMEM_BYTES>>>(x, f, out);
}

// round 5
// speedup vs baseline: 1.1242x; 1.1242x over previous
#include <cuda_runtime.h>
#include <cuda_bf16.h>

// FilterLayer: y[b,c,h,w] = sum_{i,j in 5x5} xpad[b,c,h+i,w+j] * f[b,i*5+j,h,w]
// x: [4,3,512,512] f32, f: [4,25,512,512] f32, out: [4,3,512,512] f32, pad=2.
//
// R5: R1 skeleton + register double-buffer of f tap-rows.
//  - fv[2][5] float4 ring: row i+1's 5 LDG.128 issued before row i's FMAs
//    -> ~5 outstanding global loads per warp at ALL times (sustained MLP).
//  - row-0 f loads issued before x staging (overlap tile fill latency).
//  - __launch_bounds__(256,3): reg cap ~84, 3 blocks/SM, 24 warps.

#define Hc 512
#define Wc 512
#define Bc 4
#define WIN 5
#define PAD 2

#define TILE_W 128   // 32 threads x 4 px
#define TILE_H 8
#define SW (TILE_W + 2*PAD)   // 132
#define SH (TILE_H + 2*PAD)   // 12

__global__ __launch_bounds__(256, 3)
void filter_kernel(const float* __restrict__ x,
                   const float* __restrict__ f,
                   float* __restrict__ out)
{
    __shared__ float sx[3][SH][SW];   // 19008 B

    const int tx = threadIdx.x;       // 0..31
    const int ty = threadIdx.y;       // 0..7
    const int tid = ty * 32 + tx;
    const int b  = blockIdx.z;
    const int h0 = blockIdx.y * TILE_H;
    const int w0 = blockIdx.x * TILE_W;

    const int h = h0 + ty;
    const int w = w0 + tx * 4;

    const float* fbase = f + ((long)(b * (WIN*WIN)) * Hc + h) * Wc + w;

    // ---- Prologue: issue f tap-row 0 loads before x staging ----
    float4 fv[2][WIN];
    #pragma unroll
    for (int j = 0; j < WIN; j++)
        fv[0][j] = *reinterpret_cast<const float4*>(fbase + (long)j * (Hc * Wc));

    // ---- Stage x tile (with zero halo) into shared ----
    const int total = 3 * SH * SW;    // 4752
    #pragma unroll 4
    for (int idx = tid; idx < total; idx += 256) {
        int c   = idx / (SH * SW);
        int rem = idx - c * (SH * SW);
        int r   = rem / SW;
        int col = rem - r * SW;
        int gh = h0 + r - PAD;
        int gw = w0 + col - PAD;
        float v = 0.0f;
        if ((unsigned)gh < Hc && (unsigned)gw < Wc)
            v = x[((b * 3 + c) * Hc + gh) * Wc + gw];
        sx[c][r][col] = v;
    }
    __syncthreads();

    float acc[3][4];
    #pragma unroll
    for (int c = 0; c < 3; c++)
        #pragma unroll
        for (int p = 0; p < 4; p++)
            acc[c][p] = 0.0f;

    #pragma unroll
    for (int i = 0; i < WIN; i++) {
        const int cur = i & 1;
        const int nxt = cur ^ 1;

        // Prefetch next tap-row's filter vectors (in flight during FMAs below)
        if (i + 1 < WIN) {
            #pragma unroll
            for (int j = 0; j < WIN; j++)
                fv[nxt][j] = *reinterpret_cast<const float4*>(
                    fbase + (long)((i + 1) * WIN + j) * (Hc * Wc));
        }

        #pragma unroll
        for (int c = 0; c < 3; c++) {
            const float* row = &sx[c][ty + i][tx * 4];
            const float4 a  = *reinterpret_cast<const float4*>(row);
            const float4 bb = *reinterpret_cast<const float4*>(row + 4);
            float xr[8];
            xr[0] = a.x;  xr[1] = a.y;  xr[2] = a.z;  xr[3] = a.w;
            xr[4] = bb.x; xr[5] = bb.y; xr[6] = bb.z; xr[7] = bb.w;

            #pragma unroll
            for (int j = 0; j < WIN; j++) {
                acc[c][0] = fmaf(xr[0 + j], fv[cur][j].x, acc[c][0]);
                acc[c][1] = fmaf(xr[1 + j], fv[cur][j].y, acc[c][1]);
                acc[c][2] = fmaf(xr[2 + j], fv[cur][j].z, acc[c][2]);
                acc[c][3] = fmaf(xr[3 + j], fv[cur][j].w, acc[c][3]);
            }
        }
    }

    #pragma unroll
    for (int c = 0; c < 3; c++) {
        float4 o;
        o.x = acc[c][0]; o.y = acc[c][1]; o.z = acc[c][2]; o.w = acc[c][3];
        __stcs(reinterpret_cast<float4*>(out + ((long)(b * 3 + c) * Hc + h) * Wc + w), o);
    }
}

extern "C" void kernel_launch(void* const* d_in, const int* in_sizes, int n_in,
                              void* d_out, int out_size)
{
    const float* x = (const float*)d_in[0];
    const float* f = (const float*)d_in[1];
    float* out = (float*)d_out;

    dim3 block(32, 8, 1);
    dim3 grid(Wc / TILE_W, Hc / TILE_H, Bc);
    filter_kernel<<<grid, block>>>(x, f, out);
}

// round 10
// speedup vs baseline: 1.4747x; 1.3119x over previous
#include <cuda_runtime.h>
#include <cuda_bf16.h>

// FilterLayer: y[b,c,h,w] = sum_{i,j in 5x5} xpad[b,c,h+i,w+j] * f[b,i*5+j,h,w]
// x: [4,3,512,512] f32, f: [4,25,512,512] f32, out: [4,3,512,512] f32, pad=2.
//
// R6: occupancy push. Evidence: bench time tracks occupancy (33%->33us,
// 41%->31us, 47%->27.2us). Shrink per-thread state: 2 px/thread, float2 f
// loads, 512-thread blocks, __launch_bounds__(512,3) -> 42-reg cap ->
// 3 blocks/SM = 48 warps. Same smem x-tile + __ldcs(f)/__stcs(out) as the
// R2 champion.

#define Hc 512
#define Wc 512
#define Bc 4
#define WIN 5
#define PAD 2

#define TILE_W 128   // 64 threads x 2 px
#define TILE_H 8
#define SW (TILE_W + 2*PAD)   // 132
#define SH (TILE_H + 2*PAD)   // 12

__global__ __launch_bounds__(512, 3)
void filter_kernel(const float* __restrict__ x,
                   const float* __restrict__ f,
                   float* __restrict__ out)
{
    __shared__ float sx[3][SH][SW];   // 19008 B

    const int tx = threadIdx.x;       // 0..63
    const int ty = threadIdx.y;       // 0..7
    const int tid = ty * 64 + tx;     // 0..511
    const int b  = blockIdx.z;
    const int h0 = blockIdx.y * TILE_H;
    const int w0 = blockIdx.x * TILE_W;

    // ---- Stage x tile (with zero halo) into shared ----
    const int total = 3 * SH * SW;    // 4752
    #pragma unroll 3
    for (int idx = tid; idx < total; idx += 512) {
        int c   = idx / (SH * SW);
        int rem = idx - c * (SH * SW);
        int r   = rem / SW;
        int col = rem - r * SW;
        int gh = h0 + r - PAD;
        int gw = w0 + col - PAD;
        float v = 0.0f;
        if ((unsigned)gh < Hc && (unsigned)gw < Wc)
            v = x[((b * 3 + c) * Hc + gh) * Wc + gw];
        sx[c][r][col] = v;
    }
    __syncthreads();

    const int h = h0 + ty;
    const int w = w0 + tx * 2;

    float acc[3][2];
    #pragma unroll
    for (int c = 0; c < 3; c++) {
        acc[c][0] = 0.0f;
        acc[c][1] = 0.0f;
    }

    const float* fbase = f + ((long)(b * (WIN*WIN)) * Hc + h) * Wc + w;

    #pragma unroll
    for (int i = 0; i < WIN; i++) {
        // Batch-load this tap row's 5 filter float2s (stream-once)
        float2 fv[WIN];
        #pragma unroll
        for (int j = 0; j < WIN; j++)
            fv[j] = __ldcs(reinterpret_cast<const float2*>(
                        fbase + (long)(i * WIN + j) * (Hc * Wc)));

        #pragma unroll
        for (int c = 0; c < 3; c++) {
            // 6 consecutive x values for this (c, tap-row): 3 aligned float2s
            const float* row = &sx[c][ty + i][tx * 2];
            const float2 a0 = *reinterpret_cast<const float2*>(row);
            const float2 a1 = *reinterpret_cast<const float2*>(row + 2);
            const float2 a2 = *reinterpret_cast<const float2*>(row + 4);
            float xr[6];
            xr[0] = a0.x; xr[1] = a0.y;
            xr[2] = a1.x; xr[3] = a1.y;
            xr[4] = a2.x; xr[5] = a2.y;

            #pragma unroll
            for (int j = 0; j < WIN; j++) {
                acc[c][0] = fmaf(xr[0 + j], fv[j].x, acc[c][0]);
                acc[c][1] = fmaf(xr[1 + j], fv[j].y, acc[c][1]);
            }
        }
    }

    #pragma unroll
    for (int c = 0; c < 3; c++) {
        float2 o;
        o.x = acc[c][0];
        o.y = acc[c][1];
        __stcs(reinterpret_cast<float2*>(out + ((long)(b * 3 + c) * Hc + h) * Wc + w), o);
    }
}

extern "C" void kernel_launch(void* const* d_in, const int* in_sizes, int n_in,
                              void* d_out, int out_size)
{
    const float* x = (const float*)d_in[0];
    const float* f = (const float*)d_in[1];
    float* out = (float*)d_out;

    dim3 block(64, 8, 1);
    dim3 grid(Wc / TILE_W, Hc / TILE_H, Bc);
    filter_kernel<<<grid, block>>>(x, f, out);
}

// round 12
// speedup vs baseline: 1.4766x; 1.0013x over previous
#include <cuda_runtime.h>
#include <cuda_bf16.h>

// FilterLayer: y[b,c,h,w] = sum_{i,j in 5x5} xpad[b,c,h+i,w+j] * f[b,i*5+j,h,w]
// x: [4,3,512,512] f32, f: [4,25,512,512] f32, out: [4,3,512,512] f32, pad=2.
//
// R7: 4 blocks/SM occupancy push (time has tracked warp count every round).
// Register diet to fit the 32-reg cap of __launch_bounds__(512,4):
//  - per tap-row: xr[18] (3 channels x 6 floats) loaded from smem first,
//    then j-loop does one float2 f load + 6 FMAs (no fv[5] batch buffer).
//  - 2 px/thread, 512-thread blocks, 19KB smem x-tile, __ldcs/__stcs.
// Target: 64 warps/SM (~84% occ), DRAM ~70-75%, ~21-22us.

#define Hc 512
#define Wc 512
#define Bc 4
#define WIN 5
#define PAD 2

#define TILE_W 128   // 64 threads x 2 px
#define TILE_H 8
#define SW (TILE_W + 2*PAD)   // 132
#define SH (TILE_H + 2*PAD)   // 12

__global__ __launch_bounds__(512, 4)
void filter_kernel(const float* __restrict__ x,
                   const float* __restrict__ f,
                   float* __restrict__ out)
{
    __shared__ float sx[3][SH][SW];   // 19008 B

    const int tx = threadIdx.x;       // 0..63
    const int ty = threadIdx.y;       // 0..7
    const int tid = ty * 64 + tx;     // 0..511
    const int b  = blockIdx.z;
    const int h0 = blockIdx.y * TILE_H;
    const int w0 = blockIdx.x * TILE_W;

    // ---- Stage x tile (with zero halo) into shared ----
    const int total = 3 * SH * SW;    // 4752
    #pragma unroll 3
    for (int idx = tid; idx < total; idx += 512) {
        int c   = idx / (SH * SW);
        int rem = idx - c * (SH * SW);
        int r   = rem / SW;
        int col = rem - r * SW;
        int gh = h0 + r - PAD;
        int gw = w0 + col - PAD;
        float v = 0.0f;
        if ((unsigned)gh < Hc && (unsigned)gw < Wc)
            v = x[((b * 3 + c) * Hc + gh) * Wc + gw];
        sx[c][r][col] = v;
    }
    __syncthreads();

    const int h = h0 + ty;
    const int w = w0 + tx * 2;

    float acc[3][2];
    #pragma unroll
    for (int c = 0; c < 3; c++) {
        acc[c][0] = 0.0f;
        acc[c][1] = 0.0f;
    }

    const float* fbase = f + ((long)(b * (WIN*WIN)) * Hc + h) * Wc + w;

    #pragma unroll
    for (int i = 0; i < WIN; i++) {
        // All 3 channels' 6-wide x windows for this tap row (LDS, cheap)
        float xr[3][6];
        #pragma unroll
        for (int c = 0; c < 3; c++) {
            const float* row = &sx[c][ty + i][tx * 2];
            const float2 a0 = *reinterpret_cast<const float2*>(row);
            const float2 a1 = *reinterpret_cast<const float2*>(row + 2);
            const float2 a2 = *reinterpret_cast<const float2*>(row + 4);
            xr[c][0] = a0.x; xr[c][1] = a0.y;
            xr[c][2] = a1.x; xr[c][3] = a1.y;
            xr[c][4] = a2.x; xr[c][5] = a2.y;
        }

        #pragma unroll
        for (int j = 0; j < WIN; j++) {
            const float2 fv = __ldcs(reinterpret_cast<const float2*>(
                                  fbase + (long)(i * WIN + j) * (Hc * Wc)));
            #pragma unroll
            for (int c = 0; c < 3; c++) {
                acc[c][0] = fmaf(xr[c][0 + j], fv.x, acc[c][0]);
                acc[c][1] = fmaf(xr[c][1 + j], fv.y, acc[c][1]);
            }
        }
    }

    #pragma unroll
    for (int c = 0; c < 3; c++) {
        float2 o;
        o.x = acc[c][0];
        o.y = acc[c][1];
        __stcs(reinterpret_cast<float2*>(out + ((long)(b * 3 + c) * Hc + h) * Wc + w), o);
    }
}

extern "C" void kernel_launch(void* const* d_in, const int* in_sizes, int n_in,
                              void* d_out, int out_size)
{
    const float* x = (const float*)d_in[0];
    const float* f = (const float*)d_in[1];
    float* out = (float*)d_out;

    dim3 block(64, 8, 1);
    dim3 grid(Wc / TILE_W, Hc / TILE_H, Bc);
    filter_kernel<<<grid, block>>>(x, f, out);
}